// round 1
// baseline (speedup 1.0000x reference)
#include <cuda_runtime.h>
#include <math.h>

// mask[i][j] = ((i > j) || (i/nn == j/nn)) && (i != j)
// Row-closed form: end_i = (i/nn + 1)*nn ; mask[i][j] = (j < end_i) && (j != i)
//
// Pure store-bound: 8192x8192 fp32 = 256 MB written. Use float4 stores,
// one per thread, 2D grid (x: float4 column chunks, y: rows).

__global__ void create_mask_vec4_kernel(const int* __restrict__ nn_ptr,
                                        float4* __restrict__ out,
                                        int n, int row_q /* n/4 */) {
    const int j4 = blockIdx.x * blockDim.x + threadIdx.x;
    const int i  = blockIdx.y;
    if (j4 >= row_q) return;

    const int nn  = *nn_ptr;                 // uniform broadcast load
    const int end = (i / nn + 1) * nn;       // ones-run length for this row
    const int j0  = j4 << 2;

    float4 v;
    v.x = ((j0 + 0) < end && (j0 + 0) != i) ? 1.0f : 0.0f;
    v.y = ((j0 + 1) < end && (j0 + 1) != i) ? 1.0f : 0.0f;
    v.z = ((j0 + 2) < end && (j0 + 2) != i) ? 1.0f : 0.0f;
    v.w = ((j0 + 3) < end && (j0 + 3) != i) ? 1.0f : 0.0f;

    out[(size_t)i * row_q + j4] = v;
}

// Scalar fallback for n not divisible by 4 (not expected here, kept for safety).
__global__ void create_mask_scalar_kernel(const int* __restrict__ nn_ptr,
                                          float* __restrict__ out,
                                          int n) {
    const long long idx   = (long long)blockIdx.x * blockDim.x + threadIdx.x;
    const long long total = (long long)n * n;
    if (idx >= total) return;
    const int nn = *nn_ptr;
    const int i  = (int)(idx / n);
    const int j  = (int)(idx - (long long)i * n);
    const int end = (i / nn + 1) * nn;
    out[idx] = (j < end && j != i) ? 1.0f : 0.0f;
}

extern "C" void kernel_launch(void* const* d_in, const int* in_sizes, int n_in,
                              void* d_out, int out_size) {
    const int* nn_ptr = (const int*)d_in[0];   // n_nodes
    float* out = (float*)d_out;

    // out is the n x n mask -> n = sqrt(out_size)
    int n = (int)llround(sqrt((double)out_size));

    if ((n & 3) == 0) {
        const int row_q = n >> 2;              // float4s per row
        const int threads = 256;
        dim3 grid((row_q + threads - 1) / threads, n);
        create_mask_vec4_kernel<<<grid, threads>>>(nn_ptr, (float4*)out, n, row_q);
    } else {
        const long long total = (long long)n * n;
        const int threads = 256;
        const long long blocks = (total + threads - 1) / threads;
        create_mask_scalar_kernel<<<(unsigned)blocks, threads>>>(nn_ptr, out, n);
    }
}